// round 15
// baseline (speedup 1.0000x reference)
#include <cuda_runtime.h>
#include <cuda_bf16.h>
#include <cstdint>

#define N_NODES 50000
#define E_EDGES 1600000
#define M_TOTAL (E_EDGES + N_NODES)
#define NT32 ((M_TOTAL + 31) / 32)     // 51563 warp-units of 32 msgs
#define EU32 (E_EDGES / 32)            // 50000 exact: units >= this are self-loops
#define GRID_MSG 304

__device__ float g_agg[N_NODES * 64];
__device__ float g_YS[N_NODES * 64];   // x@W1[:32] + b1 + pos@W1[32:35]
__device__ float g_P[N_NODES * 64];    // pos@W1[32:35]
__device__ int g_ei_is64;
__device__ int g_tile;

// ---------------------------------------------------------------------------
__device__ __forceinline__ uint32_t smem_u32(const void* p) {
    uint32_t a;
    asm("{ .reg .u64 t; cvta.to.shared.u64 t, %1; cvt.u32.u64 %0, t; }" : "=r"(a) : "l"(p));
    return a;
}
__device__ __forceinline__ void ldsm4(uint32_t* r, uint32_t addr) {
    asm volatile("ldmatrix.sync.aligned.m8n8.x4.shared.b16 {%0,%1,%2,%3}, [%4];"
        : "=r"(r[0]), "=r"(r[1]), "=r"(r[2]), "=r"(r[3]) : "r"(addr));
}
__device__ __forceinline__ void mma_bf16(float* c, const uint32_t* a, uint32_t b0, uint32_t b1) {
    asm volatile("mma.sync.aligned.m16n8k16.row.col.f32.bf16.bf16.f32 "
        "{%0,%1,%2,%3}, {%4,%5,%6,%7}, {%8,%9}, {%0,%1,%2,%3};"
        : "+f"(c[0]), "+f"(c[1]), "+f"(c[2]), "+f"(c[3])
        : "r"(a[0]), "r"(a[1]), "r"(a[2]), "r"(a[3]), "r"(b0), "r"(b1));
}
__device__ __forceinline__ void split2(float a, float b, uint32_t& hi, uint32_t& lo) {
    __nv_bfloat162 h = __floats2bfloat162_rn(a, b);
    float ra = a - __bfloat162float(h.x);
    float rb = b - __bfloat162float(h.y);
    __nv_bfloat162 l = __floats2bfloat162_rn(ra, rb);
    hi = *(uint32_t*)&h; lo = *(uint32_t*)&l;
}

// ---------------------------------------------------------------------------
__global__ void k_detect(const int* __restrict__ ei_raw) {
    __shared__ int any_nonzero;
    if (threadIdx.x == 0) any_nonzero = 0;
    __syncthreads();
    int w = ei_raw[2 * threadIdx.x + 1];
    if (w != 0) atomicOr(&any_nonzero, 1);
    __syncthreads();
    if (threadIdx.x == 0) g_ei_is64 = any_nonzero ? 0 : 1;
}

__global__ void k_zero() {
    int i = blockIdx.x * blockDim.x + threadIdx.x;
    if (i == 0) g_tile = 0;
    if (i < N_NODES * 64 / 4)
        ((float4*)g_agg)[i] = make_float4(0.f, 0.f, 0.f, 0.f);
}

// ---------------------------------------------------------------------------
// k_pre: per node, fp32-exact:
//   Y1 = x @ W1[:32] + b1 ; P = pos @ W1[32:35] ; YS = Y1 + P
// ---------------------------------------------------------------------------
#define SPX 0
#define SPW (64 * 36)
#define SPT (SPW + 32 * 64)
#define SMEM_PRE_BYTES ((SPT + 192) * 4)

__global__ __launch_bounds__(128) void k_pre(
    const float* __restrict__ x, const float* __restrict__ pos,
    const float* __restrict__ W1, const float* __restrict__ b1)
{
    extern __shared__ float sm[];
    float* sX = sm + SPX;
    float* sW = sm + SPW;
    float* sWT = sm + SPT;
    const int tid = threadIdx.x;
    const int nbase = blockIdx.x * 64;

    for (int i = tid; i < 32 * 16; i += 128)
        ((float4*)sW)[i] = __ldg((const float4*)W1 + i);
    if (tid < 64) {
        sWT[tid]       = W1[32 * 64 + tid];
        sWT[64 + tid]  = W1[33 * 64 + tid];
        sWT[128 + tid] = W1[34 * 64 + tid];
    }
    for (int idx = tid; idx < 64 * 8; idx += 128) {
        int r = idx >> 3, c4 = idx & 7;
        float4 v = make_float4(0.f, 0.f, 0.f, 0.f);
        if (nbase + r < N_NODES)
            v = *(const float4*)(x + (size_t)(nbase + r) * 32 + c4 * 4);
        *(float4*)(sX + r * 36 + c4 * 4) = v;
    }
    __syncthreads();

    const int tx = tid & 7, ty = tid >> 3;
    const int fbase = tx * 8;
    float acc[4][8];
    float bj[8];
    #pragma unroll
    for (int j = 0; j < 8; j++) bj[j] = __ldg(&b1[fbase + j]);
    #pragma unroll
    for (int i = 0; i < 4; i++)
        #pragma unroll
        for (int j = 0; j < 8; j++) acc[i][j] = bj[j];

    for (int k4 = 0; k4 < 8; k4++) {
        const int k0 = k4 * 4;
        float4 wv[4][2];
        #pragma unroll
        for (int kk = 0; kk < 4; kk++) {
            wv[kk][0] = *(const float4*)(sW + (k0 + kk) * 64 + fbase);
            wv[kk][1] = *(const float4*)(sW + (k0 + kk) * 64 + fbase + 4);
        }
        #pragma unroll
        for (int i = 0; i < 4; i++) {
            float4 av = *(const float4*)(sX + (ty + 16 * i) * 36 + k0);
            float a4[4] = {av.x, av.y, av.z, av.w};
            #pragma unroll
            for (int kk = 0; kk < 4; kk++) {
                const float* w = &wv[kk][0].x;
                #pragma unroll
                for (int j = 0; j < 8; j++)
                    acc[i][j] = fmaf(a4[kk], w[j], acc[i][j]);
            }
        }
    }
    #pragma unroll
    for (int i = 0; i < 4; i++) {
        int n = nbase + ty + 16 * i;
        if (n < N_NODES) {
            float p0 = pos[n * 3 + 0], p1 = pos[n * 3 + 1], p2 = pos[n * 3 + 2];
            float pv[8], ys[8];
            #pragma unroll
            for (int j = 0; j < 8; j++) {
                int c = fbase + j;
                pv[j] = fmaf(p0, sWT[c], fmaf(p1, sWT[64 + c], p2 * sWT[128 + c]));
                ys[j] = acc[i][j] + pv[j];
            }
            *(float4*)(g_YS + (size_t)n * 64 + fbase)     = make_float4(ys[0], ys[1], ys[2], ys[3]);
            *(float4*)(g_YS + (size_t)n * 64 + fbase + 4) = make_float4(ys[4], ys[5], ys[6], ys[7]);
            *(float4*)(g_P  + (size_t)n * 64 + fbase)     = make_float4(pv[0], pv[1], pv[2], pv[3]);
            *(float4*)(g_P  + (size_t)n * 64 + fbase + 4) = make_float4(pv[4], pv[5], pv[6], pv[7]);
        }
    }
}

// ---------------------------------------------------------------------------
// k_msg: warp-autonomous, 32-msg units (2 m-tiles, B amortized). Epilogue
// stages relu(out) fp32 into the warp-private H1 region (alias) and issues
// COALESCED atomics: 1 cache line per 32-col half per message.
// ---------------------------------------------------------------------------
#define O_W2_HI  0                      // 64 rows x 144 B
#define O_W2_LO  9216
#define O_B2     18432                  // 64 fp32
#define O_H1     18688                  // 8 warps x 9216 (HI 4608 | LO 4608), 32 rows x 144B
#define SMEM_MSG_BYTES (18688 + 8 * 9216)   // 92416

__global__ __launch_bounds__(256, 2) void k_msg(
    const void* __restrict__ ei_raw,
    const float* __restrict__ W2, const float* __restrict__ bias2)
{
    extern __shared__ char smc[];
    const uint32_t smb = smem_u32(smc);
    uint32_t* W2_HI = (uint32_t*)(smc + O_W2_HI);
    uint32_t* W2_LO = (uint32_t*)(smc + O_W2_LO);
    float* sB2 = (float*)(smc + O_B2);

    const int tid = threadIdx.x;
    const int wid = tid >> 5;
    const int lid = tid & 31;

    // ---- stage W2^T split + b2 (once per CTA) ----
    for (int i = tid; i < 64 * 32; i += 256) {
        int n = i / 32, w = i % 32, k = 2 * w;
        uint32_t hi, lo; split2(W2[k * 64 + n], W2[(k + 1) * 64 + n], hi, lo);
        W2_HI[n * 36 + w] = hi; W2_LO[n * 36 + w] = lo;
    }
    if (tid < 64) sB2[tid] = bias2[tid];
    const int is64 = g_ei_is64;
    __syncthreads();   // last block barrier

    // warp-private H1 block: HI at h1w, LO at h1w + 4608; sOut aliases it
    const uint32_t h1w = smb + O_H1 + wid * 9216;
    float* sOutW = (float*)(smc + O_H1 + wid * 9216);   // stride 66 fp32

    // lane roles
    const int q    = lid & 15;           // index-load: message within 16
    const int half = lid >> 4;           // 0 = src, 1 = dst
    const int gb_m = lid >> 4;           // gather: msg within pair-of-2
    const int gb_h = (lid >> 3) & 1;     //         half-row
    const int gb_s = lid & 7;            //         16B segment
    const int arow  = lid & 15;
    const int akoff = (lid >> 4) * 8;
    const int bnrow = (lid & 7) + ((lid & 16) ? 8 : 0);
    const int bk = ((lid >> 3) & 1) * 8;
    const int cq = lid & 3;

    // hoisted bias pairs (loop-invariant)
    float bb[8][2];
    #pragma unroll
    for (int nb = 0; nb < 8; nb++) {
        bb[nb][0] = sB2[8 * nb + 2 * cq];
        bb[nb][1] = sB2[8 * nb + 2 * cq + 1];
    }

    for (;;) {
        int u;
        if (lid == 0) u = atomicAdd(&g_tile, 1);
        u = __shfl_sync(0xffffffffu, u, 0);
        if (u >= NT32) break;

        // ---- index load: idx0 = msgs 0-15, idx1 = msgs 16-31 ----
        int idx0, idx1;
        if (u < EU32) {
            int m0 = u * 32 + q;
            int m1 = m0 + 16;
            if (is64) {
                idx0 = (int)((const long long*)ei_raw)[(size_t)half * E_EDGES + m0];
                idx1 = (int)((const long long*)ei_raw)[(size_t)half * E_EDGES + m1];
            } else {
                idx0 = ((const int*)ei_raw)[(size_t)half * E_EDGES + m0];
                idx1 = ((const int*)ei_raw)[(size_t)half * E_EDGES + m1];
            }
            if ((unsigned)idx0 >= N_NODES) idx0 = 0;
            if ((unsigned)idx1 >= N_NODES) idx1 = 0;
        } else {
            int mm0 = u * 32 + q - E_EDGES;
            int mm1 = mm0 + 16;
            idx0 = (mm0 < N_NODES) ? mm0 : -1;
            idx1 = (mm1 < N_NODES) ? mm1 : -1;
        }

        // ---- gather: 32 rows: relu(YS[src]-P[dst]) -> split -> H1 ----
        #pragma unroll
        for (int it = 0; it < 16; it++) {
            int j = it * 2 + gb_m;                  // row 0..31
            int iv = (j < 16) ? idx0 : idx1;
            int src = __shfl_sync(0xffffffffu, iv, j & 15);
            int dst = __shfl_sync(0xffffffffu, iv, 16 + (j & 15));
            int s = src < 0 ? 0 : src;
            int d = dst < 0 ? 0 : dst;
            int n0 = gb_h * 32 + gb_s * 4;
            float4 ys = __ldg((const float4*)(g_YS + (size_t)s * 64 + n0));
            float4 pp = __ldg((const float4*)(g_P  + (size_t)d * 64 + n0));
            float v0 = fmaxf(ys.x - pp.x, 0.f);
            float v1 = fmaxf(ys.y - pp.y, 0.f);
            float v2 = fmaxf(ys.z - pp.z, 0.f);
            float v3 = fmaxf(ys.w - pp.w, 0.f);
            uint32_t a, b, c, d2;
            split2(v0, v1, a, b);
            split2(v2, v3, c, d2);
            uint32_t off = (uint32_t)(j * 144 + gb_h * 64 + gb_s * 8);
            *(uint2*)(smc + (h1w - smb) + off)        = make_uint2(a, c);
            *(uint2*)(smc + (h1w - smb) + 4608 + off) = make_uint2(b, d2);
        }
        __syncwarp();

        // ---- GEMM: 32 msgs x 64 cols, K=64, bf16 3-pass ----
        float acc[2][8][4];
        #pragma unroll
        for (int mt = 0; mt < 2; mt++)
            #pragma unroll
            for (int nb = 0; nb < 8; nb++) {
                acc[mt][nb][0] = bb[nb][0]; acc[mt][nb][1] = bb[nb][1];
                acc[mt][nb][2] = bb[nb][0]; acc[mt][nb][3] = bb[nb][1];
            }
        #pragma unroll
        for (int kc = 0; kc < 4; kc++) {
            const int k0 = kc * 16;
            uint32_t ahi[2][4], alo[2][4];
            #pragma unroll
            for (int mt = 0; mt < 2; mt++) {
                uint32_t aaddr = h1w + (mt * 16 + arow) * 144 + (k0 + akoff) * 2;
                ldsm4(ahi[mt], aaddr);
                ldsm4(alo[mt], aaddr + 4608);
            }
            #pragma unroll
            for (int hf = 0; hf < 4; hf++) {
                uint32_t bhi[4], blo[4];
                uint32_t baddr = smb + O_W2_HI + (hf * 16 + bnrow) * 144 + (k0 + bk) * 2;
                ldsm4(bhi, baddr);
                ldsm4(blo, baddr + (O_W2_LO - O_W2_HI));
                #pragma unroll
                for (int mt = 0; mt < 2; mt++)
                    #pragma unroll
                    for (int t = 0; t < 2; t++) {
                        int nb = hf * 2 + t;
                        mma_bf16(acc[mt][nb], ahi[mt], bhi[2 * t], bhi[2 * t + 1]);
                        mma_bf16(acc[mt][nb], alo[mt], bhi[2 * t], bhi[2 * t + 1]);
                        mma_bf16(acc[mt][nb], ahi[mt], blo[2 * t], blo[2 * t + 1]);
                    }
            }
        }
        __syncwarp();   // all H1 ldsm reads done before sOut (alias) writes

        // ---- epilogue: relu -> sOutW (fp32, stride 66, warp-private) ----
        {
            int rA = lid >> 2;
            #pragma unroll
            for (int mt = 0; mt < 2; mt++)
                #pragma unroll
                for (int nb = 0; nb < 8; nb++) {
                    int c = 8 * nb + 2 * cq;
                    int r0 = mt * 16 + rA;
                    *(float2*)(sOutW + r0 * 66 + c) =
                        make_float2(fmaxf(acc[mt][nb][0], 0.f), fmaxf(acc[mt][nb][1], 0.f));
                    *(float2*)(sOutW + (r0 + 8) * 66 + c) =
                        make_float2(fmaxf(acc[mt][nb][2], 0.f), fmaxf(acc[mt][nb][3], 0.f));
                }
        }
        __syncwarp();

        // ---- coalesced predicated max scatter: 1 line per 32-col half ----
        #pragma unroll 4
        for (int j = 0; j < 32; j++) {
            int iv = (j < 16) ? idx0 : idx1;
            int dst = __shfl_sync(0xffffffffu, iv, 16 + (j & 15));
            if (dst < 0) continue;
            float v0 = sOutW[j * 66 + lid];
            float v1 = sOutW[j * 66 + 32 + lid];
            int* ap = (int*)g_agg + (size_t)dst * 64;
            if (v0 > 0.f) atomicMax(ap + lid,      __float_as_int(v0));
            if (v1 > 0.f) atomicMax(ap + 32 + lid, __float_as_int(v1));
        }
        __syncwarp();   // sOut reads done before next unit's gather overwrites
    }
}

// ---------------------------------------------------------------------------
// k_out: out = agg @ Wg + bg    [50000,64] x [64,128]
// ---------------------------------------------------------------------------
#define SMO_A 0
#define SMO_W (64 * 68)
#define SMEM_OUT_BYTES ((64 * 68 + 64 * 128) * 4)

__global__ __launch_bounds__(128) void k_out(
    const float* __restrict__ Wg, const float* __restrict__ bg,
    float* __restrict__ out)
{
    extern __shared__ float sm[];
    float* sA = sm + SMO_A;
    float* sW = sm + SMO_W;
    const int tid = threadIdx.x;
    const int nbase = blockIdx.x * 64;

    {
        float4* dst4 = (float4*)sW;
        const float4* src4 = (const float4*)Wg;
        for (int i = tid; i < 64 * 32; i += 128) dst4[i] = __ldg(src4 + i);
    }
    for (int idx = tid; idx < 64 * 16; idx += 128) {
        int rr = idx >> 4, c4 = idx & 15;
        float4 v = make_float4(0.f, 0.f, 0.f, 0.f);
        if (nbase + rr < N_NODES)
            v = *(const float4*)(g_agg + (size_t)(nbase + rr) * 64 + c4 * 4);
        *(float4*)(sA + rr * 68 + c4 * 4) = v;
    }
    __syncthreads();

    const int tx = tid & 15;
    const int ty = tid >> 4;
    const int fbase = tx * 8;

    float acc[8][8];
    float bj[8];
    #pragma unroll
    for (int j = 0; j < 8; j++) bj[j] = __ldg(&bg[fbase + j]);
    #pragma unroll
    for (int i = 0; i < 8; i++)
        #pragma unroll
        for (int j = 0; j < 8; j++) acc[i][j] = bj[j];

    for (int k4 = 0; k4 < 16; k4++) {
        const int k0 = k4 * 4;
        float4 wv[4][2];
        #pragma unroll
        for (int kk = 0; kk < 4; kk++) {
            wv[kk][0] = *(const float4*)(sW + (k0 + kk) * 128 + fbase);
            wv[kk][1] = *(const float4*)(sW + (k0 + kk) * 128 + fbase + 4);
        }
        #pragma unroll
        for (int i = 0; i < 8; i++) {
            float4 av = *(const float4*)(sA + (ty + 8 * i) * 68 + k0);
            float a4[4] = {av.x, av.y, av.z, av.w};
            #pragma unroll
            for (int kk = 0; kk < 4; kk++) {
                const float* w = &wv[kk][0].x;
                #pragma unroll
                for (int j = 0; j < 8; j++)
                    acc[i][j] = fmaf(a4[kk], w[j], acc[i][j]);
            }
        }
    }

    #pragma unroll
    for (int i = 0; i < 8; i++) {
        int n = nbase + ty + 8 * i;
        if (n < N_NODES) {
            float4 v0, v1;
            v0.x = acc[i][0]; v0.y = acc[i][1]; v0.z = acc[i][2]; v0.w = acc[i][3];
            v1.x = acc[i][4]; v1.y = acc[i][5]; v1.z = acc[i][6]; v1.w = acc[i][7];
            *(float4*)(out + (size_t)n * 128 + fbase)     = v0;
            *(float4*)(out + (size_t)n * 128 + fbase + 4) = v1;
        }
    }
}

// ---------------------------------------------------------------------------
extern "C" void kernel_launch(void* const* d_in, const int* in_sizes, int n_in,
                              void* d_out, int out_size) {
    const float* x   = (const float*)d_in[0];
    const float* pos = (const float*)d_in[1];
    const void*  ei  = d_in[2];
    const float* W1  = (const float*)d_in[3];
    const float* b1  = (const float*)d_in[4];
    const float* W2  = (const float*)d_in[5];
    const float* b2  = (const float*)d_in[6];
    const float* Wg  = (const float*)d_in[7];
    const float* bg  = (const float*)d_in[8];
    float* out = (float*)d_out;

    cudaFuncSetAttribute(k_msg, cudaFuncAttributeMaxDynamicSharedMemorySize, SMEM_MSG_BYTES);
    cudaFuncSetAttribute(k_out, cudaFuncAttributeMaxDynamicSharedMemorySize, SMEM_OUT_BYTES);
    cudaFuncSetAttribute(k_pre, cudaFuncAttributeMaxDynamicSharedMemorySize, SMEM_PRE_BYTES);

    k_detect<<<1, 1024>>>((const int*)ei);
    k_zero<<<(N_NODES * 64 / 4 + 255) / 256, 256>>>();
    k_pre<<<(N_NODES + 63) / 64, 128, SMEM_PRE_BYTES>>>(x, pos, W1, b1);
    k_msg<<<GRID_MSG, 256, SMEM_MSG_BYTES>>>(ei, W2, b2);
    k_out<<<(N_NODES + 63) / 64, 128, SMEM_OUT_BYTES>>>(Wg, bg, out);
}

// round 16
// speedup vs baseline: 1.0829x; 1.0829x over previous
#include <cuda_runtime.h>
#include <cuda_bf16.h>
#include <cstdint>

#define N_NODES 50000
#define E_EDGES 1600000
#define M_TOTAL (E_EDGES + N_NODES)
#define NT32 ((M_TOTAL + 31) / 32)     // 51563 warp-units of 32 msgs
#define EU32 (E_EDGES / 32)            // 50000 exact: units >= this are self-loops
#define GRID_MSG 304

__device__ float g_agg[N_NODES * 64];
__device__ float g_YS[N_NODES * 64];   // x@W1[:32] + b1 + pos@W1[32:35]
__device__ float g_P[N_NODES * 64];    // pos@W1[32:35]
__device__ int g_ei_is64;
__device__ int g_tile;

// ---------------------------------------------------------------------------
__device__ __forceinline__ uint32_t smem_u32(const void* p) {
    uint32_t a;
    asm("{ .reg .u64 t; cvta.to.shared.u64 t, %1; cvt.u32.u64 %0, t; }" : "=r"(a) : "l"(p));
    return a;
}
__device__ __forceinline__ void ldsm4(uint32_t* r, uint32_t addr) {
    asm volatile("ldmatrix.sync.aligned.m8n8.x4.shared.b16 {%0,%1,%2,%3}, [%4];"
        : "=r"(r[0]), "=r"(r[1]), "=r"(r[2]), "=r"(r[3]) : "r"(addr));
}
__device__ __forceinline__ void mma_bf16(float* c, const uint32_t* a, uint32_t b0, uint32_t b1) {
    asm volatile("mma.sync.aligned.m16n8k16.row.col.f32.bf16.bf16.f32 "
        "{%0,%1,%2,%3}, {%4,%5,%6,%7}, {%8,%9}, {%0,%1,%2,%3};"
        : "+f"(c[0]), "+f"(c[1]), "+f"(c[2]), "+f"(c[3])
        : "r"(a[0]), "r"(a[1]), "r"(a[2]), "r"(a[3]), "r"(b0), "r"(b1));
}
__device__ __forceinline__ void split2(float a, float b, uint32_t& hi, uint32_t& lo) {
    __nv_bfloat162 h = __floats2bfloat162_rn(a, b);
    float ra = a - __bfloat162float(h.x);
    float rb = b - __bfloat162float(h.y);
    __nv_bfloat162 l = __floats2bfloat162_rn(ra, rb);
    hi = *(uint32_t*)&h; lo = *(uint32_t*)&l;
}

// ---------------------------------------------------------------------------
// k_zero: zero agg + reset tile counter + (block 0) detect edge dtype.
// int64 little-endian indices < 50000 => all odd 32-bit words zero; a real
// int32 edge list has ~0 probability of 256 zero dst entries.
// ---------------------------------------------------------------------------
__global__ void k_zero(const int* __restrict__ ei_raw) {
    int i = blockIdx.x * blockDim.x + threadIdx.x;
    if (i == 0) g_tile = 0;
    if (blockIdx.x == 0) {
        __shared__ int any_nonzero;
        if (threadIdx.x == 0) any_nonzero = 0;
        __syncthreads();
        if (ei_raw[2 * threadIdx.x + 1] != 0) atomicOr(&any_nonzero, 1);
        __syncthreads();
        if (threadIdx.x == 0) g_ei_is64 = any_nonzero ? 0 : 1;
    }
    if (i < N_NODES * 64 / 4)
        ((float4*)g_agg)[i] = make_float4(0.f, 0.f, 0.f, 0.f);
}

// ---------------------------------------------------------------------------
// k_pre: per node, fp32-exact:
//   Y1 = x @ W1[:32] + b1 ; P = pos @ W1[32:35] ; YS = Y1 + P
// ---------------------------------------------------------------------------
#define SPX 0
#define SPW (64 * 36)
#define SPT (SPW + 32 * 64)
#define SMEM_PRE_BYTES ((SPT + 192) * 4)

__global__ __launch_bounds__(128) void k_pre(
    const float* __restrict__ x, const float* __restrict__ pos,
    const float* __restrict__ W1, const float* __restrict__ b1)
{
    extern __shared__ float sm[];
    float* sX = sm + SPX;
    float* sW = sm + SPW;
    float* sWT = sm + SPT;
    const int tid = threadIdx.x;
    const int nbase = blockIdx.x * 64;

    for (int i = tid; i < 32 * 16; i += 128)
        ((float4*)sW)[i] = __ldg((const float4*)W1 + i);
    if (tid < 64) {
        sWT[tid]       = W1[32 * 64 + tid];
        sWT[64 + tid]  = W1[33 * 64 + tid];
        sWT[128 + tid] = W1[34 * 64 + tid];
    }
    for (int idx = tid; idx < 64 * 8; idx += 128) {
        int r = idx >> 3, c4 = idx & 7;
        float4 v = make_float4(0.f, 0.f, 0.f, 0.f);
        if (nbase + r < N_NODES)
            v = *(const float4*)(x + (size_t)(nbase + r) * 32 + c4 * 4);
        *(float4*)(sX + r * 36 + c4 * 4) = v;
    }
    __syncthreads();

    const int tx = tid & 7, ty = tid >> 3;
    const int fbase = tx * 8;
    float acc[4][8];
    float bj[8];
    #pragma unroll
    for (int j = 0; j < 8; j++) bj[j] = __ldg(&b1[fbase + j]);
    #pragma unroll
    for (int i = 0; i < 4; i++)
        #pragma unroll
        for (int j = 0; j < 8; j++) acc[i][j] = bj[j];

    for (int k4 = 0; k4 < 8; k4++) {
        const int k0 = k4 * 4;
        float4 wv[4][2];
        #pragma unroll
        for (int kk = 0; kk < 4; kk++) {
            wv[kk][0] = *(const float4*)(sW + (k0 + kk) * 64 + fbase);
            wv[kk][1] = *(const float4*)(sW + (k0 + kk) * 64 + fbase + 4);
        }
        #pragma unroll
        for (int i = 0; i < 4; i++) {
            float4 av = *(const float4*)(sX + (ty + 16 * i) * 36 + k0);
            float a4[4] = {av.x, av.y, av.z, av.w};
            #pragma unroll
            for (int kk = 0; kk < 4; kk++) {
                const float* w = &wv[kk][0].x;
                #pragma unroll
                for (int j = 0; j < 8; j++)
                    acc[i][j] = fmaf(a4[kk], w[j], acc[i][j]);
            }
        }
    }
    #pragma unroll
    for (int i = 0; i < 4; i++) {
        int n = nbase + ty + 16 * i;
        if (n < N_NODES) {
            float p0 = pos[n * 3 + 0], p1 = pos[n * 3 + 1], p2 = pos[n * 3 + 2];
            float pv[8], ys[8];
            #pragma unroll
            for (int j = 0; j < 8; j++) {
                int c = fbase + j;
                pv[j] = fmaf(p0, sWT[c], fmaf(p1, sWT[64 + c], p2 * sWT[128 + c]));
                ys[j] = acc[i][j] + pv[j];
            }
            *(float4*)(g_YS + (size_t)n * 64 + fbase)     = make_float4(ys[0], ys[1], ys[2], ys[3]);
            *(float4*)(g_YS + (size_t)n * 64 + fbase + 4) = make_float4(ys[4], ys[5], ys[6], ys[7]);
            *(float4*)(g_P  + (size_t)n * 64 + fbase)     = make_float4(pv[0], pv[1], pv[2], pv[3]);
            *(float4*)(g_P  + (size_t)n * 64 + fbase + 4) = make_float4(pv[4], pv[5], pv[6], pv[7]);
        }
    }
}

// ---------------------------------------------------------------------------
// k_msg (R14 config — measured best): warp-autonomous, 32-msg units
// (2 m-tiles, B amortized), epilogue atomics DIRECT from accumulators.
// ---------------------------------------------------------------------------
#define O_W2_HI  0                      // 64 rows x 144 B
#define O_W2_LO  9216
#define O_B2     18432                  // 64 fp32
#define O_H1     18688                  // 8 warps x 9216 (HI 4608 | LO 4608), 32 rows x 144B
#define SMEM_MSG_BYTES (18688 + 8 * 9216)   // 92416

__global__ __launch_bounds__(256, 2) void k_msg(
    const void* __restrict__ ei_raw,
    const float* __restrict__ W2, const float* __restrict__ bias2)
{
    extern __shared__ char smc[];
    const uint32_t smb = smem_u32(smc);
    uint32_t* W2_HI = (uint32_t*)(smc + O_W2_HI);
    uint32_t* W2_LO = (uint32_t*)(smc + O_W2_LO);
    float* sB2 = (float*)(smc + O_B2);

    const int tid = threadIdx.x;
    const int wid = tid >> 5;
    const int lid = tid & 31;

    // ---- stage W2^T split + b2 (once per CTA) ----
    for (int i = tid; i < 64 * 32; i += 256) {
        int n = i / 32, w = i % 32, k = 2 * w;
        uint32_t hi, lo; split2(W2[k * 64 + n], W2[(k + 1) * 64 + n], hi, lo);
        W2_HI[n * 36 + w] = hi; W2_LO[n * 36 + w] = lo;
    }
    if (tid < 64) sB2[tid] = bias2[tid];
    const int is64 = g_ei_is64;
    __syncthreads();   // last block barrier

    // warp-private H1 block: HI at h1w, LO at h1w + 4608
    const uint32_t h1w = smb + O_H1 + wid * 9216;

    // lane roles
    const int q    = lid & 15;           // index-load: message within 16
    const int half = lid >> 4;           // 0 = src, 1 = dst
    const int gb_m = lid >> 4;           // gather: msg within pair-of-2
    const int gb_h = (lid >> 3) & 1;     //         half-row
    const int gb_s = lid & 7;            //         16B segment
    const int arow  = lid & 15;
    const int akoff = (lid >> 4) * 8;
    const int bnrow = (lid & 7) + ((lid & 16) ? 8 : 0);
    const int bk = ((lid >> 3) & 1) * 8;
    const int cq = lid & 3;

    // hoisted bias pairs for this lane's columns (loop-invariant)
    float bb[8][2];
    #pragma unroll
    for (int nb = 0; nb < 8; nb++) {
        bb[nb][0] = sB2[8 * nb + 2 * cq];
        bb[nb][1] = sB2[8 * nb + 2 * cq + 1];
    }

    for (;;) {
        int u;
        if (lid == 0) u = atomicAdd(&g_tile, 1);
        u = __shfl_sync(0xffffffffu, u, 0);
        if (u >= NT32) break;

        // ---- index load: idx0 = msgs 0-15, idx1 = msgs 16-31 ----
        // lanes 0-15 hold src, 16-31 hold dst; -1 marks invalid (skip atomic)
        int idx0, idx1;
        if (u < EU32) {
            int m0 = u * 32 + q;
            int m1 = m0 + 16;
            if (is64) {
                idx0 = (int)((const long long*)ei_raw)[(size_t)half * E_EDGES + m0];
                idx1 = (int)((const long long*)ei_raw)[(size_t)half * E_EDGES + m1];
            } else {
                idx0 = ((const int*)ei_raw)[(size_t)half * E_EDGES + m0];
                idx1 = ((const int*)ei_raw)[(size_t)half * E_EDGES + m1];
            }
            if ((unsigned)idx0 >= N_NODES) idx0 = 0;
            if ((unsigned)idx1 >= N_NODES) idx1 = 0;
        } else {
            int mm0 = u * 32 + q - E_EDGES;
            int mm1 = mm0 + 16;
            idx0 = (mm0 < N_NODES) ? mm0 : -1;
            idx1 = (mm1 < N_NODES) ? mm1 : -1;
        }

        // ---- gather: 32 rows: relu(YS[src]-P[dst]) -> split -> H1 ----
        #pragma unroll
        for (int it = 0; it < 16; it++) {
            int j = it * 2 + gb_m;                  // row 0..31
            int iv = (j < 16) ? idx0 : idx1;
            int src = __shfl_sync(0xffffffffu, iv, j & 15);
            int dst = __shfl_sync(0xffffffffu, iv, 16 + (j & 15));
            int s = src < 0 ? 0 : src;
            int d = dst < 0 ? 0 : dst;
            int n0 = gb_h * 32 + gb_s * 4;
            float4 ys = __ldg((const float4*)(g_YS + (size_t)s * 64 + n0));
            float4 pp = __ldg((const float4*)(g_P  + (size_t)d * 64 + n0));
            float v0 = fmaxf(ys.x - pp.x, 0.f);
            float v1 = fmaxf(ys.y - pp.y, 0.f);
            float v2 = fmaxf(ys.z - pp.z, 0.f);
            float v3 = fmaxf(ys.w - pp.w, 0.f);
            uint32_t a, b, c, d2;
            split2(v0, v1, a, b);
            split2(v2, v3, c, d2);
            uint32_t off = (uint32_t)(j * 144 + gb_h * 64 + gb_s * 8);
            *(uint2*)(smc + (h1w - smb) + off)        = make_uint2(a, c);
            *(uint2*)(smc + (h1w - smb) + 4608 + off) = make_uint2(b, d2);
        }
        __syncwarp();

        // ---- GEMM: 32 msgs x 64 cols, K=64, bf16 3-pass ----
        float acc[2][8][4];
        #pragma unroll
        for (int mt = 0; mt < 2; mt++)
            #pragma unroll
            for (int nb = 0; nb < 8; nb++) {
                acc[mt][nb][0] = bb[nb][0]; acc[mt][nb][1] = bb[nb][1];
                acc[mt][nb][2] = bb[nb][0]; acc[mt][nb][3] = bb[nb][1];
            }
        #pragma unroll
        for (int kc = 0; kc < 4; kc++) {
            const int k0 = kc * 16;
            uint32_t ahi[2][4], alo[2][4];
            #pragma unroll
            for (int mt = 0; mt < 2; mt++) {
                uint32_t aaddr = h1w + (mt * 16 + arow) * 144 + (k0 + akoff) * 2;
                ldsm4(ahi[mt], aaddr);
                ldsm4(alo[mt], aaddr + 4608);
            }
            #pragma unroll
            for (int hf = 0; hf < 4; hf++) {
                uint32_t bhi[4], blo[4];
                uint32_t baddr = smb + O_W2_HI + (hf * 16 + bnrow) * 144 + (k0 + bk) * 2;
                ldsm4(bhi, baddr);
                ldsm4(blo, baddr + (O_W2_LO - O_W2_HI));
                #pragma unroll
                for (int mt = 0; mt < 2; mt++)
                    #pragma unroll
                    for (int t = 0; t < 2; t++) {
                        int nb = hf * 2 + t;
                        mma_bf16(acc[mt][nb], ahi[mt], bhi[2 * t], bhi[2 * t + 1]);
                        mma_bf16(acc[mt][nb], alo[mt], bhi[2 * t], bhi[2 * t + 1]);
                        mma_bf16(acc[mt][nb], ahi[mt], blo[2 * t], blo[2 * t + 1]);
                    }
            }
        }
        __syncwarp();   // H1 ldsm reads complete before next unit's gather

        // ---- epilogue: relu + atomicMax DIRECT from accumulators ----
        {
            int rA = lid >> 2;
            #pragma unroll
            for (int mt = 0; mt < 2; mt++) {
                int iv = mt ? idx1 : idx0;
                int dst0 = __shfl_sync(0xffffffffu, iv, 16 + rA);
                int dst1 = __shfl_sync(0xffffffffu, iv, 16 + rA + 8);
                #pragma unroll
                for (int nb = 0; nb < 8; nb++) {
                    int c = 8 * nb + 2 * cq;
                    float v0 = fmaxf(acc[mt][nb][0], 0.f);
                    float v1 = fmaxf(acc[mt][nb][1], 0.f);
                    float v2 = fmaxf(acc[mt][nb][2], 0.f);
                    float v3 = fmaxf(acc[mt][nb][3], 0.f);
                    if (dst0 >= 0) {
                        int* ap = (int*)g_agg + (size_t)dst0 * 64 + c;
                        if (v0 > 0.f) atomicMax(ap,     __float_as_int(v0));
                        if (v1 > 0.f) atomicMax(ap + 1, __float_as_int(v1));
                    }
                    if (dst1 >= 0) {
                        int* ap = (int*)g_agg + (size_t)dst1 * 64 + c;
                        if (v2 > 0.f) atomicMax(ap,     __float_as_int(v2));
                        if (v3 > 0.f) atomicMax(ap + 1, __float_as_int(v3));
                    }
                }
            }
        }
    }
}

// ---------------------------------------------------------------------------
// k_out: out = agg @ Wg + bg    [50000,64] x [64,128]
// 256 threads, 64 nodes/block, 4-node x 8-col thread tile -> lower regs,
// 24 warps/SM (was 16) for latency hiding.
// ---------------------------------------------------------------------------
#define SMO_A 0
#define SMO_W (64 * 68)
#define SMEM_OUT_BYTES ((64 * 68 + 64 * 128) * 4)

__global__ __launch_bounds__(256, 3) void k_out(
    const float* __restrict__ Wg, const float* __restrict__ bg,
    float* __restrict__ out)
{
    extern __shared__ float sm[];
    float* sA = sm + SMO_A;
    float* sW = sm + SMO_W;
    const int tid = threadIdx.x;
    const int nbase = blockIdx.x * 64;

    {
        float4* dst4 = (float4*)sW;
        const float4* src4 = (const float4*)Wg;
        for (int i = tid; i < 64 * 32; i += 256) dst4[i] = __ldg(src4 + i);
    }
    for (int idx = tid; idx < 64 * 16; idx += 256) {
        int rr = idx >> 4, c4 = idx & 15;
        float4 v = make_float4(0.f, 0.f, 0.f, 0.f);
        if (nbase + rr < N_NODES)
            v = *(const float4*)(g_agg + (size_t)(nbase + rr) * 64 + c4 * 4);
        *(float4*)(sA + rr * 68 + c4 * 4) = v;
    }
    __syncthreads();

    const int tx = tid & 15;     // 16 col groups of 8 = 128 cols
    const int ty = tid >> 4;     // 16 node groups; node = ty + 16*i, i<4
    const int fbase = tx * 8;

    float acc[4][8];
    float bj[8];
    #pragma unroll
    for (int j = 0; j < 8; j++) bj[j] = __ldg(&bg[fbase + j]);
    #pragma unroll
    for (int i = 0; i < 4; i++)
        #pragma unroll
        for (int j = 0; j < 8; j++) acc[i][j] = bj[j];

    for (int k4 = 0; k4 < 16; k4++) {
        const int k0 = k4 * 4;
        float4 wv[4][2];
        #pragma unroll
        for (int kk = 0; kk < 4; kk++) {
            wv[kk][0] = *(const float4*)(sW + (k0 + kk) * 128 + fbase);
            wv[kk][1] = *(const float4*)(sW + (k0 + kk) * 128 + fbase + 4);
        }
        #pragma unroll
        for (int i = 0; i < 4; i++) {
            float4 av = *(const float4*)(sA + (ty + 16 * i) * 68 + k0);
            float a4[4] = {av.x, av.y, av.z, av.w};
            #pragma unroll
            for (int kk = 0; kk < 4; kk++) {
                const float* w = &wv[kk][0].x;
                #pragma unroll
                for (int j = 0; j < 8; j++)
                    acc[i][j] = fmaf(a4[kk], w[j], acc[i][j]);
            }
        }
    }

    #pragma unroll
    for (int i = 0; i < 4; i++) {
        int n = nbase + ty + 16 * i;
        if (n < N_NODES) {
            float4 v0, v1;
            v0.x = acc[i][0]; v0.y = acc[i][1]; v0.z = acc[i][2]; v0.w = acc[i][3];
            v1.x = acc[i][4]; v1.y = acc[i][5]; v1.z = acc[i][6]; v1.w = acc[i][7];
            *(float4*)(out + (size_t)n * 128 + fbase)     = v0;
            *(float4*)(out + (size_t)n * 128 + fbase + 4) = v1;
        }
    }
}

// ---------------------------------------------------------------------------
extern "C" void kernel_launch(void* const* d_in, const int* in_sizes, int n_in,
                              void* d_out, int out_size) {
    const float* x   = (const float*)d_in[0];
    const float* pos = (const float*)d_in[1];
    const void*  ei  = d_in[2];
    const float* W1  = (const float*)d_in[3];
    const float* b1  = (const float*)d_in[4];
    const float* W2  = (const float*)d_in[5];
    const float* b2  = (const float*)d_in[6];
    const float* Wg  = (const float*)d_in[7];
    const float* bg  = (const float*)d_in[8];
    float* out = (float*)d_out;

    cudaFuncSetAttribute(k_msg, cudaFuncAttributeMaxDynamicSharedMemorySize, SMEM_MSG_BYTES);
    cudaFuncSetAttribute(k_out, cudaFuncAttributeMaxDynamicSharedMemorySize, SMEM_OUT_BYTES);
    cudaFuncSetAttribute(k_pre, cudaFuncAttributeMaxDynamicSharedMemorySize, SMEM_PRE_BYTES);

    k_zero<<<(N_NODES * 64 / 4 + 255) / 256, 256>>>((const int*)ei);
    k_pre<<<(N_NODES + 63) / 64, 128, SMEM_PRE_BYTES>>>(x, pos, W1, b1);
    k_msg<<<GRID_MSG, 256, SMEM_MSG_BYTES>>>(ei, W2, b2);
    k_out<<<(N_NODES + 63) / 64, 256, SMEM_OUT_BYTES>>>(Wg, bg, out);
}

// round 17
// speedup vs baseline: 1.0885x; 1.0051x over previous
#include <cuda_runtime.h>
#include <cuda_bf16.h>
#include <cstdint>

#define N_NODES 50000
#define E_EDGES 1600000
#define M_TOTAL (E_EDGES + N_NODES)
#define NT32 ((M_TOTAL + 31) / 32)     // 51563 warp-units of 32 msgs
#define EU32 (E_EDGES / 32)            // 50000 exact: units >= this are self-loops
#define GRID_MSG 304

__device__ float g_agg[N_NODES * 64];
__device__ float g_YS[N_NODES * 64];   // x@W1[:32] + b1 + pos@W1[32:35]
__device__ float g_P[N_NODES * 64];    // pos@W1[32:35]
__device__ int g_ei_is64;
__device__ int g_tile;

// ---------------------------------------------------------------------------
__device__ __forceinline__ uint32_t smem_u32(const void* p) {
    uint32_t a;
    asm("{ .reg .u64 t; cvta.to.shared.u64 t, %1; cvt.u32.u64 %0, t; }" : "=r"(a) : "l"(p));
    return a;
}
__device__ __forceinline__ void ldsm4(uint32_t* r, uint32_t addr) {
    asm volatile("ldmatrix.sync.aligned.m8n8.x4.shared.b16 {%0,%1,%2,%3}, [%4];"
        : "=r"(r[0]), "=r"(r[1]), "=r"(r[2]), "=r"(r[3]) : "r"(addr));
}
__device__ __forceinline__ void mma_bf16(float* c, const uint32_t* a, uint32_t b0, uint32_t b1) {
    asm volatile("mma.sync.aligned.m16n8k16.row.col.f32.bf16.bf16.f32 "
        "{%0,%1,%2,%3}, {%4,%5,%6,%7}, {%8,%9}, {%0,%1,%2,%3};"
        : "+f"(c[0]), "+f"(c[1]), "+f"(c[2]), "+f"(c[3])
        : "r"(a[0]), "r"(a[1]), "r"(a[2]), "r"(a[3]), "r"(b0), "r"(b1));
}
__device__ __forceinline__ void split2(float a, float b, uint32_t& hi, uint32_t& lo) {
    __nv_bfloat162 h = __floats2bfloat162_rn(a, b);
    float ra = a - __bfloat162float(h.x);
    float rb = b - __bfloat162float(h.y);
    __nv_bfloat162 l = __floats2bfloat162_rn(ra, rb);
    hi = *(uint32_t*)&h; lo = *(uint32_t*)&l;
}

// ---------------------------------------------------------------------------
// k_zero: zero agg + reset tile counter + (block 0) detect edge dtype.
// ---------------------------------------------------------------------------
__global__ void k_zero(const int* __restrict__ ei_raw) {
    int i = blockIdx.x * blockDim.x + threadIdx.x;
    if (i == 0) g_tile = 0;
    if (blockIdx.x == 0) {
        __shared__ int any_nonzero;
        if (threadIdx.x == 0) any_nonzero = 0;
        __syncthreads();
        if (ei_raw[2 * threadIdx.x + 1] != 0) atomicOr(&any_nonzero, 1);
        __syncthreads();
        if (threadIdx.x == 0) g_ei_is64 = any_nonzero ? 0 : 1;
    }
    if (i < N_NODES * 64 / 4)
        ((float4*)g_agg)[i] = make_float4(0.f, 0.f, 0.f, 0.f);
}

// ---------------------------------------------------------------------------
// k_pre: per node, fp32-exact:
//   Y1 = x @ W1[:32] + b1 ; P = pos @ W1[32:35] ; YS = Y1 + P
// ---------------------------------------------------------------------------
#define SPX 0
#define SPW (64 * 36)
#define SPT (SPW + 32 * 64)
#define SMEM_PRE_BYTES ((SPT + 192) * 4)

__global__ __launch_bounds__(128) void k_pre(
    const float* __restrict__ x, const float* __restrict__ pos,
    const float* __restrict__ W1, const float* __restrict__ b1)
{
    extern __shared__ float sm[];
    float* sX = sm + SPX;
    float* sW = sm + SPW;
    float* sWT = sm + SPT;
    const int tid = threadIdx.x;
    const int nbase = blockIdx.x * 64;

    for (int i = tid; i < 32 * 16; i += 128)
        ((float4*)sW)[i] = __ldg((const float4*)W1 + i);
    if (tid < 64) {
        sWT[tid]       = W1[32 * 64 + tid];
        sWT[64 + tid]  = W1[33 * 64 + tid];
        sWT[128 + tid] = W1[34 * 64 + tid];
    }
    for (int idx = tid; idx < 64 * 8; idx += 128) {
        int r = idx >> 3, c4 = idx & 7;
        float4 v = make_float4(0.f, 0.f, 0.f, 0.f);
        if (nbase + r < N_NODES)
            v = *(const float4*)(x + (size_t)(nbase + r) * 32 + c4 * 4);
        *(float4*)(sX + r * 36 + c4 * 4) = v;
    }
    __syncthreads();

    const int tx = tid & 7, ty = tid >> 3;
    const int fbase = tx * 8;
    float acc[4][8];
    float bj[8];
    #pragma unroll
    for (int j = 0; j < 8; j++) bj[j] = __ldg(&b1[fbase + j]);
    #pragma unroll
    for (int i = 0; i < 4; i++)
        #pragma unroll
        for (int j = 0; j < 8; j++) acc[i][j] = bj[j];

    for (int k4 = 0; k4 < 8; k4++) {
        const int k0 = k4 * 4;
        float4 wv[4][2];
        #pragma unroll
        for (int kk = 0; kk < 4; kk++) {
            wv[kk][0] = *(const float4*)(sW + (k0 + kk) * 64 + fbase);
            wv[kk][1] = *(const float4*)(sW + (k0 + kk) * 64 + fbase + 4);
        }
        #pragma unroll
        for (int i = 0; i < 4; i++) {
            float4 av = *(const float4*)(sX + (ty + 16 * i) * 36 + k0);
            float a4[4] = {av.x, av.y, av.z, av.w};
            #pragma unroll
            for (int kk = 0; kk < 4; kk++) {
                const float* w = &wv[kk][0].x;
                #pragma unroll
                for (int j = 0; j < 8; j++)
                    acc[i][j] = fmaf(a4[kk], w[j], acc[i][j]);
            }
        }
    }
    #pragma unroll
    for (int i = 0; i < 4; i++) {
        int n = nbase + ty + 16 * i;
        if (n < N_NODES) {
            float p0 = pos[n * 3 + 0], p1 = pos[n * 3 + 1], p2 = pos[n * 3 + 2];
            float pv[8], ys[8];
            #pragma unroll
            for (int j = 0; j < 8; j++) {
                int c = fbase + j;
                pv[j] = fmaf(p0, sWT[c], fmaf(p1, sWT[64 + c], p2 * sWT[128 + c]));
                ys[j] = acc[i][j] + pv[j];
            }
            *(float4*)(g_YS + (size_t)n * 64 + fbase)     = make_float4(ys[0], ys[1], ys[2], ys[3]);
            *(float4*)(g_YS + (size_t)n * 64 + fbase + 4) = make_float4(ys[4], ys[5], ys[6], ys[7]);
            *(float4*)(g_P  + (size_t)n * 64 + fbase)     = make_float4(pv[0], pv[1], pv[2], pv[3]);
            *(float4*)(g_P  + (size_t)n * 64 + fbase + 4) = make_float4(pv[4], pv[5], pv[6], pv[7]);
        }
    }
}

// ---------------------------------------------------------------------------
// k_msg (R14 pipeline + next-unit prefetch): warp-autonomous, 32-msg units,
// epilogue atomics direct from accumulators. Steal+index-LDG for unit u+1
// issues BEFORE the GEMM of unit u, hiding ~600cyc of steal latency.
// ---------------------------------------------------------------------------
#define O_W2_HI  0                      // 64 rows x 144 B
#define O_W2_LO  9216
#define O_B2     18432                  // 64 fp32
#define O_H1     18688                  // 8 warps x 9216 (HI 4608 | LO 4608), 32 rows x 144B
#define SMEM_MSG_BYTES (18688 + 8 * 9216)   // 92416

__global__ __launch_bounds__(256, 2) void k_msg(
    const void* __restrict__ ei_raw,
    const float* __restrict__ W2, const float* __restrict__ bias2)
{
    extern __shared__ char smc[];
    const uint32_t smb = smem_u32(smc);
    uint32_t* W2_HI = (uint32_t*)(smc + O_W2_HI);
    uint32_t* W2_LO = (uint32_t*)(smc + O_W2_LO);
    float* sB2 = (float*)(smc + O_B2);

    const int tid = threadIdx.x;
    const int wid = tid >> 5;
    const int lid = tid & 31;

    // ---- stage W2^T split + b2 (once per CTA) ----
    for (int i = tid; i < 64 * 32; i += 256) {
        int n = i / 32, w = i % 32, k = 2 * w;
        uint32_t hi, lo; split2(W2[k * 64 + n], W2[(k + 1) * 64 + n], hi, lo);
        W2_HI[n * 36 + w] = hi; W2_LO[n * 36 + w] = lo;
    }
    if (tid < 64) sB2[tid] = bias2[tid];
    const int is64 = g_ei_is64;
    __syncthreads();   // last block barrier

    const uint32_t h1w = smb + O_H1 + wid * 9216;

    // lane roles
    const int q    = lid & 15;
    const int half = lid >> 4;
    const int gb_m = lid >> 4;
    const int gb_h = (lid >> 3) & 1;
    const int gb_s = lid & 7;
    const int arow  = lid & 15;
    const int akoff = (lid >> 4) * 8;
    const int bnrow = (lid & 7) + ((lid & 16) ? 8 : 0);
    const int bk = ((lid >> 3) & 1) * 8;
    const int cq = lid & 3;

    // hoisted bias pairs (loop-invariant)
    float bb[8][2];
    #pragma unroll
    for (int nb = 0; nb < 8; nb++) {
        bb[nb][0] = sB2[8 * nb + 2 * cq];
        bb[nb][1] = sB2[8 * nb + 2 * cq + 1];
    }

    // index loader: lanes 0-15 get src, 16-31 get dst of 2 msg groups
    auto load_idx = [&](int uu, int& i0, int& i1) {
        if (uu < EU32) {
            int m0 = uu * 32 + q, m1 = m0 + 16;
            if (is64) {
                i0 = (int)((const long long*)ei_raw)[(size_t)half * E_EDGES + m0];
                i1 = (int)((const long long*)ei_raw)[(size_t)half * E_EDGES + m1];
            } else {
                i0 = ((const int*)ei_raw)[(size_t)half * E_EDGES + m0];
                i1 = ((const int*)ei_raw)[(size_t)half * E_EDGES + m1];
            }
            if ((unsigned)i0 >= N_NODES) i0 = 0;
            if ((unsigned)i1 >= N_NODES) i1 = 0;
        } else {
            int mm0 = uu * 32 + q - E_EDGES, mm1 = mm0 + 16;
            i0 = (mm0 < N_NODES) ? mm0 : -1;
            i1 = (mm1 < N_NODES) ? mm1 : -1;
        }
    };

    // prime: steal first unit + load its indices
    int u;
    if (lid == 0) u = atomicAdd(&g_tile, 1);
    u = __shfl_sync(0xffffffffu, u, 0);
    int idx0 = 0, idx1 = 0;
    if (u < NT32) load_idx(u, idx0, idx1);

    while (u < NT32) {
        // ---- gather: 32 rows: relu(YS[src]-P[dst]) -> split -> H1 ----
        #pragma unroll
        for (int it = 0; it < 16; it++) {
            int j = it * 2 + gb_m;
            int iv = (j < 16) ? idx0 : idx1;
            int src = __shfl_sync(0xffffffffu, iv, j & 15);
            int dst = __shfl_sync(0xffffffffu, iv, 16 + (j & 15));
            int s = src < 0 ? 0 : src;
            int d = dst < 0 ? 0 : dst;
            int n0 = gb_h * 32 + gb_s * 4;
            float4 ys = __ldg((const float4*)(g_YS + (size_t)s * 64 + n0));
            float4 pp = __ldg((const float4*)(g_P  + (size_t)d * 64 + n0));
            float v0 = fmaxf(ys.x - pp.x, 0.f);
            float v1 = fmaxf(ys.y - pp.y, 0.f);
            float v2 = fmaxf(ys.z - pp.z, 0.f);
            float v3 = fmaxf(ys.w - pp.w, 0.f);
            uint32_t a, b, c, d2;
            split2(v0, v1, a, b);
            split2(v2, v3, c, d2);
            uint32_t off = (uint32_t)(j * 144 + gb_h * 64 + gb_s * 8);
            *(uint2*)(smc + (h1w - smb) + off)        = make_uint2(a, c);
            *(uint2*)(smc + (h1w - smb) + 4608 + off) = make_uint2(b, d2);
        }
        __syncwarp();

        // ---- prefetch next unit: steal + index LDG (hidden under GEMM) ----
        int un;
        if (lid == 0) un = atomicAdd(&g_tile, 1);
        un = __shfl_sync(0xffffffffu, un, 0);
        int nx0 = 0, nx1 = 0;
        if (un < NT32) load_idx(un, nx0, nx1);

        // ---- GEMM: 32 msgs x 64 cols, K=64, bf16 3-pass ----
        float acc[2][8][4];
        #pragma unroll
        for (int mt = 0; mt < 2; mt++)
            #pragma unroll
            for (int nb = 0; nb < 8; nb++) {
                acc[mt][nb][0] = bb[nb][0]; acc[mt][nb][1] = bb[nb][1];
                acc[mt][nb][2] = bb[nb][0]; acc[mt][nb][3] = bb[nb][1];
            }
        #pragma unroll
        for (int kc = 0; kc < 4; kc++) {
            const int k0 = kc * 16;
            uint32_t ahi[2][4], alo[2][4];
            #pragma unroll
            for (int mt = 0; mt < 2; mt++) {
                uint32_t aaddr = h1w + (mt * 16 + arow) * 144 + (k0 + akoff) * 2;
                ldsm4(ahi[mt], aaddr);
                ldsm4(alo[mt], aaddr + 4608);
            }
            #pragma unroll
            for (int hf = 0; hf < 4; hf++) {
                uint32_t bhi[4], blo[4];
                uint32_t baddr = smb + O_W2_HI + (hf * 16 + bnrow) * 144 + (k0 + bk) * 2;
                ldsm4(bhi, baddr);
                ldsm4(blo, baddr + (O_W2_LO - O_W2_HI));
                #pragma unroll
                for (int mt = 0; mt < 2; mt++)
                    #pragma unroll
                    for (int t = 0; t < 2; t++) {
                        int nb = hf * 2 + t;
                        mma_bf16(acc[mt][nb], ahi[mt], bhi[2 * t], bhi[2 * t + 1]);
                        mma_bf16(acc[mt][nb], alo[mt], bhi[2 * t], bhi[2 * t + 1]);
                        mma_bf16(acc[mt][nb], ahi[mt], blo[2 * t], blo[2 * t + 1]);
                    }
            }
        }
        __syncwarp();   // H1 ldsm reads complete before next unit's gather

        // ---- epilogue: relu + atomicMax DIRECT from accumulators ----
        {
            int rA = lid >> 2;
            #pragma unroll
            for (int mt = 0; mt < 2; mt++) {
                int iv = mt ? idx1 : idx0;
                int dst0 = __shfl_sync(0xffffffffu, iv, 16 + rA);
                int dst1 = __shfl_sync(0xffffffffu, iv, 16 + rA + 8);
                #pragma unroll
                for (int nb = 0; nb < 8; nb++) {
                    int c = 8 * nb + 2 * cq;
                    float v0 = fmaxf(acc[mt][nb][0], 0.f);
                    float v1 = fmaxf(acc[mt][nb][1], 0.f);
                    float v2 = fmaxf(acc[mt][nb][2], 0.f);
                    float v3 = fmaxf(acc[mt][nb][3], 0.f);
                    if (dst0 >= 0) {
                        int* ap = (int*)g_agg + (size_t)dst0 * 64 + c;
                        if (v0 > 0.f) atomicMax(ap,     __float_as_int(v0));
                        if (v1 > 0.f) atomicMax(ap + 1, __float_as_int(v1));
                    }
                    if (dst1 >= 0) {
                        int* ap = (int*)g_agg + (size_t)dst1 * 64 + c;
                        if (v2 > 0.f) atomicMax(ap,     __float_as_int(v2));
                        if (v3 > 0.f) atomicMax(ap + 1, __float_as_int(v3));
                    }
                }
            }
        }

        u = un; idx0 = nx0; idx1 = nx1;
    }
}

// ---------------------------------------------------------------------------
// k_out: out = agg @ Wg + bg   [50000,64] x [64,128], bf16 tensor 3-pass.
// 256 threads (8 warps), 128 nodes/block; warp w owns m16-tile w x all 128 cols.
// ---------------------------------------------------------------------------
#define KO_AG_HI 0                      // 128 rows x 144 B
#define KO_AG_LO 18432
#define KO_WG_HI 36864                  // 128 n-rows x 144 B
#define KO_WG_LO 55296
#define KO_BG    73728                  // 128 fp32
#define SMEM_OUT_BYTES (KO_BG + 512)    // 74240

__global__ __launch_bounds__(256, 2) void k_out(
    const float* __restrict__ Wg, const float* __restrict__ bg,
    float* __restrict__ out)
{
    extern __shared__ char smc[];
    const uint32_t smb = smem_u32(smc);
    uint32_t* AG_HI = (uint32_t*)(smc + KO_AG_HI);
    uint32_t* AG_LO = (uint32_t*)(smc + KO_AG_LO);
    uint32_t* WG_HI = (uint32_t*)(smc + KO_WG_HI);
    uint32_t* WG_LO = (uint32_t*)(smc + KO_WG_LO);
    float* sBG = (float*)(smc + KO_BG);

    const int tid = threadIdx.x;
    const int wid = tid >> 5;
    const int lid = tid & 31;
    const int nb0 = blockIdx.x * 128;

    // ---- stage Wg^T split: WT[n][k] = Wg[k*128+n], 128 rows x 32 words ----
    for (int i = tid; i < 128 * 32; i += 256) {
        int n = i >> 5, w = i & 31, k = 2 * w;
        uint32_t hi, lo; split2(Wg[k * 128 + n], Wg[(k + 1) * 128 + n], hi, lo);
        WG_HI[n * 36 + w] = hi; WG_LO[n * 36 + w] = lo;
    }
    if (tid < 128) sBG[tid] = bg[tid];

    // ---- stage agg rows (coalesced) split -> AG: thread = (row, half) ----
    {
        int r = tid >> 1, h = tid & 1;
        int node = nb0 + r;
        const float4* ap = (const float4*)(g_agg + (size_t)(node < N_NODES ? node : 0) * 64 + h * 32);
        uint32_t* hh = AG_HI + r * 36 + h * 16;
        uint32_t* ll = AG_LO + r * 36 + h * 16;
        #pragma unroll
        for (int qq = 0; qq < 8; qq++) {
            float4 v = (node < N_NODES) ? __ldg(ap + qq) : make_float4(0.f, 0.f, 0.f, 0.f);
            uint32_t a, b, c, d;
            split2(v.x, v.y, a, b);
            split2(v.z, v.w, c, d);
            hh[2 * qq] = a; hh[2 * qq + 1] = c;
            ll[2 * qq] = b; ll[2 * qq + 1] = d;
        }
    }
    __syncthreads();

    // mma lane roles
    const int arow  = lid & 15;
    const int akoff = (lid >> 4) * 8;
    const int bnrow = (lid & 7) + ((lid & 16) ? 8 : 0);
    const int bk = ((lid >> 3) & 1) * 8;
    const int cq = lid & 3;

    // ---- GEMM: 16 rows (warp tile) x 128 cols, K=64, bf16 3-pass ----
    float acc[16][4];
    #pragma unroll
    for (int nb = 0; nb < 16; nb++) {
        float b0 = sBG[8 * nb + 2 * cq], b1 = sBG[8 * nb + 2 * cq + 1];
        acc[nb][0] = b0; acc[nb][1] = b1; acc[nb][2] = b0; acc[nb][3] = b1;
    }
    #pragma unroll
    for (int kc = 0; kc < 4; kc++) {
        const int k0 = kc * 16;
        uint32_t ahi[4], alo[4];
        uint32_t aaddr = smb + KO_AG_HI + (wid * 16 + arow) * 144 + (k0 + akoff) * 2;
        ldsm4(ahi, aaddr);
        ldsm4(alo, aaddr + (KO_AG_LO - KO_AG_HI));
        #pragma unroll
        for (int hf = 0; hf < 8; hf++) {
            uint32_t bhi[4], blo[4];
            uint32_t baddr = smb + KO_WG_HI + (hf * 16 + bnrow) * 144 + (k0 + bk) * 2;
            ldsm4(bhi, baddr);
            ldsm4(blo, baddr + (KO_WG_LO - KO_WG_HI));
            #pragma unroll
            for (int t = 0; t < 2; t++) {
                int nb = hf * 2 + t;
                mma_bf16(acc[nb], ahi, bhi[2 * t], bhi[2 * t + 1]);
                mma_bf16(acc[nb], alo, bhi[2 * t], bhi[2 * t + 1]);
                mma_bf16(acc[nb], ahi, blo[2 * t], blo[2 * t + 1]);
            }
        }
    }

    // ---- epilogue: write fp32 out ----
    {
        int rA = lid >> 2;
        int n0 = nb0 + wid * 16 + rA;
        int n1 = n0 + 8;
        #pragma unroll
        for (int nb = 0; nb < 16; nb++) {
            int c = 8 * nb + 2 * cq;
            if (n0 < N_NODES)
                *(float2*)(out + (size_t)n0 * 128 + c) = make_float2(acc[nb][0], acc[nb][1]);
            if (n1 < N_NODES)
                *(float2*)(out + (size_t)n1 * 128 + c) = make_float2(acc[nb][2], acc[nb][3]);
        }
    }
}

// ---------------------------------------------------------------------------
extern "C" void kernel_launch(void* const* d_in, const int* in_sizes, int n_in,
                              void* d_out, int out_size) {
    const float* x   = (const float*)d_in[0];
    const float* pos = (const float*)d_in[1];
    const void*  ei  = d_in[2];
    const float* W1  = (const float*)d_in[3];
    const float* b1  = (const float*)d_in[4];
    const float* W2  = (const float*)d_in[5];
    const float* b2  = (const float*)d_in[6];
    const float* Wg  = (const float*)d_in[7];
    const float* bg  = (const float*)d_in[8];
    float* out = (float*)d_out;

    cudaFuncSetAttribute(k_msg, cudaFuncAttributeMaxDynamicSharedMemorySize, SMEM_MSG_BYTES);
    cudaFuncSetAttribute(k_out, cudaFuncAttributeMaxDynamicSharedMemorySize, SMEM_OUT_BYTES);
    cudaFuncSetAttribute(k_pre, cudaFuncAttributeMaxDynamicSharedMemorySize, SMEM_PRE_BYTES);

    k_zero<<<(N_NODES * 64 / 4 + 255) / 256, 256>>>((const int*)ei);
    k_pre<<<(N_NODES + 63) / 64, 128, SMEM_PRE_BYTES>>>(x, pos, W1, b1);
    k_msg<<<GRID_MSG, 256, SMEM_MSG_BYTES>>>(ei, W2, b2);
    k_out<<<(N_NODES + 127) / 128, 256, SMEM_OUT_BYTES>>>(Wg, bg, out);
}